// round 1
// baseline (speedup 1.0000x reference)
#include <cuda_runtime.h>
#include <math.h>

// Causal GQA attention prefill: S=2048, H=32, KVH=8, D=128, fp32.
// Flash-attention-2 style tiling, fp32 FMA path (baseline for later tensor-core rounds).

#define SEQ   2048
#define NH    32
#define NKVH  8
#define REP   4          // NH / NKVH
#define HD    128
#define BM    64
#define BN    64
#define NTHREADS 256
#define PSTRIDE 68       // padded P row stride (floats), 16B-aligned, breaks bank conflicts
#define QK_SCALE 0.08838834764831845f

struct SmemLayout {
    float Qs[HD][BM];        // Q tile, transposed [d][m], pre-scaled   (32 KB)
    float Ks[HD][BN];        // K tile, transposed [d][n]               (32 KB)
    float Vs[BN][HD];        // V tile, row-major  [n][d]               (32 KB)
    float Ps[BM][PSTRIDE];   // softmax probs                           (17 KB)
};

extern __shared__ unsigned char smem_raw[];

__global__ __launch_bounds__(NTHREADS, 2)
void attn_fwd_kernel(const float* __restrict__ q,
                     const float* __restrict__ k,
                     const float* __restrict__ v,
                     float* __restrict__ out,
                     int seq_len)
{
    SmemLayout& sm = *reinterpret_cast<SmemLayout*>(smem_raw);

    // Launch heavy (large-qt) blocks first to shrink the causal tail.
    const int qt  = (gridDim.x - 1) - blockIdx.x;
    const int h   = blockIdx.y;
    const int kvh = h / REP;
    const int tid = threadIdx.x;
    const int tx  = tid & 15;   // 16 columns of threads
    const int ty  = tid >> 4;   // 16 rows of threads
    const int q0  = qt * BM;

    // ---- Load Q tile (transposed, pre-scaled) ----
    // Mapping: lane owns one row n = tid%64 and a 32-float d-chunk c = tid/64.
    // Lanes within a warp hit consecutive n -> transposed smem stores are
    // conflict-free (addr stride = 1 float across lanes for fixed d).
    {
        const int n = tid & 63;
        const int c = tid >> 6;
        const float4* gq = reinterpret_cast<const float4*>(
            q + ((size_t)(q0 + n) * NH + h) * HD + c * 32);
        #pragma unroll
        for (int j = 0; j < 8; ++j) {
            float4 val = gq[j];
            int d = c * 32 + j * 4;
            sm.Qs[d + 0][n] = val.x * QK_SCALE;
            sm.Qs[d + 1][n] = val.y * QK_SCALE;
            sm.Qs[d + 2][n] = val.z * QK_SCALE;
            sm.Qs[d + 3][n] = val.w * QK_SCALE;
        }
    }

    // Per-thread online-softmax state. Thread owns score rows m = ty*4+i and
    // output columns d = tx*8 .. tx*8+7. Row stats replicated across the 16
    // tx-lanes of each row (they live in one half-warp -> butterfly shuffles).
    float m_row[4], l_row[4];
    float acc[4][8];
    #pragma unroll
    for (int i = 0; i < 4; ++i) {
        m_row[i] = -INFINITY;
        l_row[i] = 0.f;
        #pragma unroll
        for (int j = 0; j < 8; ++j) acc[i][j] = 0.f;
    }

    const int nkt = qt + 1;   // causal: K tiles 0..qt (tile qt is the diagonal)
    for (int kt = 0; kt < nkt; ++kt) {
        __syncthreads();   // previous iter's gemm2 done with Vs/Ps

        // ---- Load K (transposed) + V tiles ----
        {
            const int n  = tid & 63;
            const int c  = tid >> 6;
            const int kn = kt * BN + n;
            const float4* gk = reinterpret_cast<const float4*>(
                k + ((size_t)kn * NKVH + kvh) * HD + c * 32);
            #pragma unroll
            for (int j = 0; j < 8; ++j) {
                float4 val = gk[j];
                int d = c * 32 + j * 4;
                sm.Ks[d + 0][n] = val.x;
                sm.Ks[d + 1][n] = val.y;
                sm.Ks[d + 2][n] = val.z;
                sm.Ks[d + 3][n] = val.w;
            }
            const float4* gv = reinterpret_cast<const float4*>(
                v + ((size_t)kn * NKVH + kvh) * HD + c * 32);
            float4* sv = reinterpret_cast<float4*>(&sm.Vs[n][c * 32]);
            #pragma unroll
            for (int j = 0; j < 8; ++j) sv[j] = gv[j];
        }
        __syncthreads();

        // ---- gemm1: S = Q K^T, 4x4 fragment per thread ----
        float s[4][4];
        #pragma unroll
        for (int i = 0; i < 4; ++i)
            #pragma unroll
            for (int j = 0; j < 4; ++j) s[i][j] = 0.f;

        #pragma unroll 4
        for (int d = 0; d < HD; ++d) {
            float4 qv = *reinterpret_cast<const float4*>(&sm.Qs[d][ty * 4]);
            float4 kv = *reinterpret_cast<const float4*>(&sm.Ks[d][tx * 4]);
            s[0][0] += qv.x * kv.x; s[0][1] += qv.x * kv.y; s[0][2] += qv.x * kv.z; s[0][3] += qv.x * kv.w;
            s[1][0] += qv.y * kv.x; s[1][1] += qv.y * kv.y; s[1][2] += qv.y * kv.z; s[1][3] += qv.y * kv.w;
            s[2][0] += qv.z * kv.x; s[2][1] += qv.z * kv.y; s[2][2] += qv.z * kv.z; s[2][3] += qv.z * kv.w;
            s[3][0] += qv.w * kv.x; s[3][1] += qv.w * kv.y; s[3][2] += qv.w * kv.z; s[3][3] += qv.w * kv.w;
        }

        // ---- Causal mask (diagonal tile only; interior tiles fully valid) ----
        if (kt == qt) {
            #pragma unroll
            for (int i = 0; i < 4; ++i) {
                const int qi = q0 + ty * 4 + i;
                #pragma unroll
                for (int j = 0; j < 4; ++j) {
                    const int kj = kt * BN + tx * 4 + j;
                    if (kj > qi) s[i][j] = -INFINITY;
                }
            }
        }

        // ---- Online softmax (per row, 16-lane butterfly within half-warp) ----
        #pragma unroll
        for (int i = 0; i < 4; ++i) {
            float mx = fmaxf(fmaxf(s[i][0], s[i][1]), fmaxf(s[i][2], s[i][3]));
            #pragma unroll
            for (int off = 8; off >= 1; off >>= 1)
                mx = fmaxf(mx, __shfl_xor_sync(0xffffffffu, mx, off));
            const float m_new = fmaxf(m_row[i], mx);
            const float alpha = __expf(m_row[i] - m_new);   // exp(-inf)=0 on first tile
            m_row[i] = m_new;

            float rs = 0.f;
            #pragma unroll
            for (int j = 0; j < 4; ++j) {
                float p = __expf(s[i][j] - m_new);
                s[i][j] = p;
                rs += p;
            }
            #pragma unroll
            for (int off = 8; off >= 1; off >>= 1)
                rs += __shfl_xor_sync(0xffffffffu, rs, off);
            l_row[i] = l_row[i] * alpha + rs;

            #pragma unroll
            for (int j = 0; j < 8; ++j) acc[i][j] *= alpha;

            *reinterpret_cast<float4*>(&sm.Ps[ty * 4 + i][tx * 4]) =
                make_float4(s[i][0], s[i][1], s[i][2], s[i][3]);
        }
        __syncthreads();

        // ---- gemm2: O += P V. Thread: rows ty*4+i, cols tx*8..+7 ----
        #pragma unroll 2
        for (int n = 0; n < BN; ++n) {
            float4 v0 = *reinterpret_cast<const float4*>(&sm.Vs[n][tx * 8]);
            float4 v1 = *reinterpret_cast<const float4*>(&sm.Vs[n][tx * 8 + 4]);
            #pragma unroll
            for (int i = 0; i < 4; ++i) {
                const float p = sm.Ps[ty * 4 + i][n];   // broadcast across tx lanes
                acc[i][0] += p * v0.x; acc[i][1] += p * v0.y;
                acc[i][2] += p * v0.z; acc[i][3] += p * v0.w;
                acc[i][4] += p * v1.x; acc[i][5] += p * v1.y;
                acc[i][6] += p * v1.z; acc[i][7] += p * v1.w;
            }
        }
    }

    // ---- Epilogue: normalize + store (coalesced float4) ----
    #pragma unroll
    for (int i = 0; i < 4; ++i) {
        const float inv = 1.f / l_row[i];
        const int row = q0 + ty * 4 + i;
        float* o = out + ((size_t)row * NH + h) * HD + tx * 8;
        *reinterpret_cast<float4*>(o) =
            make_float4(acc[i][0] * inv, acc[i][1] * inv, acc[i][2] * inv, acc[i][3] * inv);
        *reinterpret_cast<float4*>(o + 4) =
            make_float4(acc[i][4] * inv, acc[i][5] * inv, acc[i][6] * inv, acc[i][7] * inv);
    }
}

extern "C" void kernel_launch(void* const* d_in, const int* in_sizes, int n_in,
                              void* d_out, int out_size)
{
    const float* q = (const float*)d_in[0];
    const float* k = (const float*)d_in[1];
    const float* v = (const float*)d_in[2];
    float* out = (float*)d_out;

    const int seq = in_sizes[0] / (NH * HD);   // 2048 for this problem

    // Idempotent host-side attribute set (not a stream op; capture-safe).
    cudaFuncSetAttribute(attn_fwd_kernel,
                         cudaFuncAttributeMaxDynamicSharedMemorySize,
                         (int)sizeof(SmemLayout));

    dim3 grid(seq / BM, NH);
    attn_fwd_kernel<<<grid, NTHREADS, sizeof(SmemLayout)>>>(q, k, v, out, seq);
}

// round 6
// speedup vs baseline: 3.0131x; 3.0131x over previous
#include <cuda_runtime.h>
#include <cuda_fp16.h>
#include <cstdint>
#include <math.h>

// Causal GQA attention prefill, S=2048, H=32, KVH=8, D=128, fp32 I/O.
// fp16 mma.sync path with hi/lo split-compensated gemm1:
//   S = Qh*Kh + Qh*Kl + Ql*Kh   (score error ~2^-22)
//   O += P(fp16) * V(fp16)      (error ~2^-11)
// 4x1 warp tiling: each warp owns 16 full score rows (warp-local softmax).

#define NH    32
#define NKVH  8
#define HD    128
#define BM    64
#define BN    64
#define QK_SCALE 0.08838834764831845f
#define LOG2E    1.4426950408889634f

// u32-word strides, all == 4 (mod 32): conflict-free ldmatrix row patterns
#define QKSTR 68   // Q/K rows: 64 u32 data + 4 pad
#define VSTR  36   // VT rows: 32 u32 + 4 pad
#define PSTR  36

// byte offsets in dynamic smem
#define SM_QH 0
#define SM_QL 17408
#define SM_KH 34816
#define SM_KL 52224
#define SM_VT 69632
#define SM_P  88064
#define SMEM_BYTES 97280

__device__ __forceinline__ uint32_t smem_u32(const void* p) {
    uint32_t a;
    asm("{ .reg .u64 t; cvta.to.shared.u64 t, %1; cvt.u32.u64 %0, t; }" : "=r"(a) : "l"(p));
    return a;
}
__device__ __forceinline__ float ex2(float x) {
    float r; asm("ex2.approx.f32 %0, %1;" : "=f"(r) : "f"(x)); return r;
}
__device__ __forceinline__ uint32_t pack_f16x2(float lo, float hi) {
    uint32_t r; asm("cvt.rn.f16x2.f32 %0, %1, %2;" : "=r"(r) : "f"(hi), "f"(lo)); return r;
}
// split (x,y) into packed fp16 hi + packed fp16 residual lo
__device__ __forceinline__ void split_pack(float x, float y, uint32_t& hi, uint32_t& lo) {
    hi = pack_f16x2(x, y);
    __half2 h = *reinterpret_cast<__half2*>(&hi);
    float2 hf = __half22float2(h);
    lo = pack_f16x2(x - hf.x, y - hf.y);
}

#define MMA_F16(c, a, b) \
    asm volatile("mma.sync.aligned.m16n8k16.row.col.f32.f16.f16.f32 " \
                 "{%0,%1,%2,%3},{%4,%5,%6,%7},{%8,%9},{%0,%1,%2,%3};" \
        : "+f"((c)[0]), "+f"((c)[1]), "+f"((c)[2]), "+f"((c)[3]) \
        : "r"((a)[0]), "r"((a)[1]), "r"((a)[2]), "r"((a)[3]), "r"((b)[0]), "r"((b)[1]))

#define LDMX4(r, addr) \
    asm volatile("ldmatrix.sync.aligned.m8n8.x4.shared.b16 {%0,%1,%2,%3}, [%4];" \
        : "=r"((r)[0]), "=r"((r)[1]), "=r"((r)[2]), "=r"((r)[3]) : "r"(addr))

#define STSV2(addr, r0, r1) \
    asm volatile("st.shared.v2.b32 [%0], {%1,%2};" :: "r"(addr), "r"(r0), "r"(r1) : "memory")

extern __shared__ unsigned char smem_raw[];

__global__ __launch_bounds__(128, 2)
void attn_mma_kernel(const float* __restrict__ q, const float* __restrict__ k,
                     const float* __restrict__ v, float* __restrict__ out)
{
    const uint32_t sb   = smem_u32(smem_raw);
    const uint32_t qh_b = sb + SM_QH, ql_b = sb + SM_QL;
    const uint32_t kh_b = sb + SM_KH, kl_b = sb + SM_KL;
    const uint32_t vt_b = sb + SM_VT, p_b  = sb + SM_P;
    uint32_t* VT = reinterpret_cast<uint32_t*>(smem_raw + SM_VT);
    uint32_t* Pp = reinterpret_cast<uint32_t*>(smem_raw + SM_P);

    const int tid  = threadIdx.x;
    const int lane = tid & 31;
    const int wid  = tid >> 5;           // warp owns rows wid*16 .. wid*16+15
    const int g    = lane >> 2;
    const int tg   = lane & 3;

    const int qt  = (gridDim.x - 1) - blockIdx.x;   // heavy blocks first
    const int hh  = blockIdx.y;
    const int kvh = hh >> 2;
    const int q0  = qt * BM;

    // ---- Q fill (once): split fp16 hi/lo, packed pairs along d ----
    {
        const int m  = tid >> 1;
        const int dh = (tid & 1) * 64;
        const float4* gq = reinterpret_cast<const float4*>(
            q + ((size_t)(q0 + m) * NH + hh) * HD + dh);
        const float sc = QK_SCALE * LOG2E;
        #pragma unroll
        for (int j = 0; j < 16; ++j) {
            float4 val = gq[j];
            uint32_t h0, l0, h1, l1;
            split_pack(val.x * sc, val.y * sc, h0, l0);
            split_pack(val.z * sc, val.w * sc, h1, l1);
            const uint32_t off = (uint32_t)(m * QKSTR + dh / 2 + j * 2) * 4u;
            STSV2(qh_b + off, h0, h1);
            STSV2(ql_b + off, l0, l1);
        }
    }

    // Per-thread rows: hb=0 -> row wid*16+g, hb=1 -> +8
    float m_s[2] = { -INFINITY, -INFINITY };
    float l_s[2] = { 0.f, 0.f };
    float o[16][4];
    #pragma unroll
    for (int nt = 0; nt < 16; ++nt)
        #pragma unroll
        for (int j = 0; j < 4; ++j) o[nt][j] = 0.f;

    for (int kt = 0; kt <= qt; ++kt) {
        __syncthreads();   // prev iter's gemm2 done with K/VT/P

        // ---- K fill: split fp16 hi/lo, [kv][d-pairs] ----
        {
            const int kv = tid >> 1;
            const int dh = (tid & 1) * 64;
            const float4* gk = reinterpret_cast<const float4*>(
                k + ((size_t)(kt * BN + kv) * NKVH + kvh) * HD + dh);
            #pragma unroll
            for (int j = 0; j < 16; ++j) {
                float4 val = gk[j];
                uint32_t h0, l0, h1, l1;
                split_pack(val.x, val.y, h0, l0);
                split_pack(val.z, val.w, h1, l1);
                const uint32_t off = (uint32_t)(kv * QKSTR + dh / 2 + j * 2) * 4u;
                STSV2(kh_b + off, h0, h1);
                STSV2(kl_b + off, l0, l1);
            }
        }
        // ---- V fill: VT[d][p] = f16x2(V[2p][d], V[2p+1][d]) ----
        {
            const int p  = lane;
            const int dh = wid * 32;
            const float4* gv0 = reinterpret_cast<const float4*>(
                v + ((size_t)(kt * BN + 2 * p) * NKVH + kvh) * HD + dh);
            const float4* gv1 = reinterpret_cast<const float4*>(
                v + ((size_t)(kt * BN + 2 * p + 1) * NKVH + kvh) * HD + dh);
            #pragma unroll
            for (int j = 0; j < 8; ++j) {
                float4 a = gv0[j], b = gv1[j];
                const int d = dh + j * 4;
                VT[(d + 0) * VSTR + p] = pack_f16x2(a.x, b.x);
                VT[(d + 1) * VSTR + p] = pack_f16x2(a.y, b.y);
                VT[(d + 2) * VSTR + p] = pack_f16x2(a.z, b.z);
                VT[(d + 3) * VSTR + p] = pack_f16x2(a.w, b.w);
            }
        }
        __syncthreads();

        // ---- gemm1: S = Qh*Kh + Qh*Kl + Ql*Kh  (warp: 16x64) ----
        float c1[8][4];
        #pragma unroll
        for (int nt = 0; nt < 8; ++nt)
            #pragma unroll
            for (int j = 0; j < 4; ++j) c1[nt][j] = 0.f;

        #pragma unroll
        for (int kc = 0; kc < 8; ++kc) {
            uint32_t aH[4], aL[4], bH[8][2], bL[8][2];
            const uint32_t offA = (uint32_t)((wid * 16 + (lane & 15)) * QKSTR
                                             + kc * 8 + (lane >> 4) * 4) * 4u;
            LDMX4(aH, qh_b + offA);
            LDMX4(aL, ql_b + offA);
            #pragma unroll
            for (int t = 0; t < 4; ++t) {
                const uint32_t offB = (uint32_t)((t * 16 + ((lane >> 4) & 1) * 8 + (lane & 7)) * QKSTR
                                                 + kc * 8 + ((lane >> 3) & 1) * 4) * 4u;
                uint32_t rh[4], rl[4];
                LDMX4(rh, kh_b + offB);
                LDMX4(rl, kl_b + offB);
                bH[2*t][0] = rh[0]; bH[2*t][1] = rh[1]; bH[2*t+1][0] = rh[2]; bH[2*t+1][1] = rh[3];
                bL[2*t][0] = rl[0]; bL[2*t][1] = rl[1]; bL[2*t+1][0] = rl[2]; bL[2*t+1][1] = rl[3];
            }
            #pragma unroll
            for (int nt = 0; nt < 8; ++nt) {
                MMA_F16(c1[nt], aH, bH[nt]);
                MMA_F16(c1[nt], aH, bL[nt]);
                MMA_F16(c1[nt], aL, bH[nt]);
            }
        }

        // ---- mask (diag tile) + online softmax (rows warp-local) ----
        const bool diag = (kt == qt);
        #pragma unroll
        for (int hb = 0; hb < 2; ++hb) {
            const int qi = q0 + wid * 16 + g + hb * 8;
            if (diag) {
                #pragma unroll
                for (int nt = 0; nt < 8; ++nt) {
                    const int kj = kt * BN + nt * 8 + 2 * tg;
                    if (kj + 0 > qi) c1[nt][hb * 2 + 0] = -INFINITY;
                    if (kj + 1 > qi) c1[nt][hb * 2 + 1] = -INFINITY;
                }
            }
            float mx = -INFINITY;
            #pragma unroll
            for (int nt = 0; nt < 8; ++nt)
                mx = fmaxf(mx, fmaxf(c1[nt][hb * 2], c1[nt][hb * 2 + 1]));
            mx = fmaxf(mx, __shfl_xor_sync(0xffffffffu, mx, 1));
            mx = fmaxf(mx, __shfl_xor_sync(0xffffffffu, mx, 2));

            const float m_new = fmaxf(m_s[hb], mx);   // finite on diag: col<=row exists
            const float alpha = ex2(m_s[hb] - m_new);
            m_s[hb] = m_new;

            float rs = 0.f;
            #pragma unroll
            for (int nt = 0; nt < 8; ++nt) {
                float p0 = ex2(c1[nt][hb * 2 + 0] - m_new);
                float p1 = ex2(c1[nt][hb * 2 + 1] - m_new);
                c1[nt][hb * 2 + 0] = p0;
                c1[nt][hb * 2 + 1] = p1;
                rs += p0 + p1;
            }
            rs += __shfl_xor_sync(0xffffffffu, rs, 1);
            rs += __shfl_xor_sync(0xffffffffu, rs, 2);
            l_s[hb] = l_s[hb] * alpha + rs;

            #pragma unroll
            for (int nt = 0; nt < 16; ++nt) {
                o[nt][hb * 2 + 0] *= alpha;
                o[nt][hb * 2 + 1] *= alpha;
            }
        }

        // ---- P -> smem (fp16x2), warp-local rows ----
        {
            const int rl = wid * 16 + g;
            #pragma unroll
            for (int nt = 0; nt < 8; ++nt) {
                const int wc = nt * 4 + tg;
                Pp[(rl + 0) * PSTR + wc] = pack_f16x2(c1[nt][0], c1[nt][1]);
                Pp[(rl + 8) * PSTR + wc] = pack_f16x2(c1[nt][2], c1[nt][3]);
            }
        }
        __syncwarp();   // P rows are warp-local; warp-scope sync suffices

        // ---- gemm2: O += P V (fp16) ----
        uint32_t aP[4][4];
        #pragma unroll
        for (int kc = 0; kc < 4; ++kc) {
            const uint32_t addr = p_b +
                (uint32_t)((wid * 16 + (lane & 15)) * PSTR + (lane >> 4) * 4 + kc * 8) * 4u;
            LDMX4(aP[kc], addr);
        }
        #pragma unroll
        for (int kc = 0; kc < 4; ++kc) {
            #pragma unroll
            for (int t = 0; t < 8; ++t) {
                const uint32_t offV = (uint32_t)((t * 16 + ((lane >> 4) & 1) * 8 + (lane & 7)) * VSTR
                                                 + kc * 8 + ((lane >> 3) & 1) * 4) * 4u;
                uint32_t rv[4];
                LDMX4(rv, vt_b + offV);
                uint32_t b0[2] = { rv[0], rv[1] }, b1[2] = { rv[2], rv[3] };
                MMA_F16(o[2 * t + 0], aP[kc], b0);
                MMA_F16(o[2 * t + 1], aP[kc], b1);
            }
        }
    }

    // ---- Epilogue: normalize, store ----
    #pragma unroll
    for (int hb = 0; hb < 2; ++hb) {
        const float inv = 1.f / l_s[hb];
        const int grow = q0 + wid * 16 + g + hb * 8;
        float* obase = out + ((size_t)grow * NH + hh) * HD + 2 * tg;
        #pragma unroll
        for (int nt = 0; nt < 16; ++nt) {
            float2 val = make_float2(o[nt][hb * 2 + 0] * inv,
                                     o[nt][hb * 2 + 1] * inv);
            *reinterpret_cast<float2*>(obase + nt * 8) = val;
        }
    }
}

extern "C" void kernel_launch(void* const* d_in, const int* in_sizes, int n_in,
                              void* d_out, int out_size)
{
    const float* q = (const float*)d_in[0];
    const float* k = (const float*)d_in[1];
    const float* v = (const float*)d_in[2];
    float* out = (float*)d_out;

    const int seq = in_sizes[0] / (NH * HD);

    cudaFuncSetAttribute(attn_mma_kernel,
                         cudaFuncAttributeMaxDynamicSharedMemorySize, SMEM_BYTES);

    dim3 grid(seq / BM, NH);
    attn_mma_kernel<<<grid, 128, SMEM_BYTES>>>(q, k, v, out);
}

// round 8
// speedup vs baseline: 3.3931x; 1.1261x over previous
#include <cuda_runtime.h>
#include <cuda_fp16.h>
#include <cstdint>
#include <math.h>

// Causal GQA attention prefill, S=2048, H=32, KVH=8, D=128, fp32 I/O.
// fp16 mma.sync path, one-sided compensated gemm1:
//   S = (Qh + Ql)*Kh = Qh*Kh + Ql*Kh   (K-quantization error only, ~3.7e-4)
//   O += P(fp16) * V(fp16)
// 4x1 warp tiling: each warp owns 16 full score rows (warp-local softmax).

#define NH    32
#define NKVH  8
#define HD    128
#define BM    64
#define BN    64
#define QK_SCALE 0.08838834764831845f
#define LOG2E    1.4426950408889634f

// u32-word strides, all == 4 (mod 32): conflict-free ldmatrix row patterns
#define QKSTR 68   // Q/K rows: 64 u32 data + 4 pad
#define VSTR  36   // VT rows: 32 u32 + 4 pad
#define PSTR  36

// byte offsets in dynamic smem
#define SM_QH 0
#define SM_QL 17408
#define SM_KH 34816
#define SM_VT 52224
#define SM_P  70656
#define SMEM_BYTES 79872

__device__ __forceinline__ uint32_t smem_u32(const void* p) {
    uint32_t a;
    asm("{ .reg .u64 t; cvta.to.shared.u64 t, %1; cvt.u32.u64 %0, t; }" : "=r"(a) : "l"(p));
    return a;
}
__device__ __forceinline__ float ex2(float x) {
    float r; asm("ex2.approx.f32 %0, %1;" : "=f"(r) : "f"(x)); return r;
}
__device__ __forceinline__ uint32_t pack_f16x2(float lo, float hi) {
    uint32_t r; asm("cvt.rn.f16x2.f32 %0, %1, %2;" : "=r"(r) : "f"(hi), "f"(lo)); return r;
}
// split (x,y) into packed fp16 hi + packed fp16 residual lo
__device__ __forceinline__ void split_pack(float x, float y, uint32_t& hi, uint32_t& lo) {
    hi = pack_f16x2(x, y);
    __half2 h = *reinterpret_cast<__half2*>(&hi);
    float2 hf = __half22float2(h);
    lo = pack_f16x2(x - hf.x, y - hf.y);
}

#define MMA_F16(c, a, b) \
    asm volatile("mma.sync.aligned.m16n8k16.row.col.f32.f16.f16.f32 " \
                 "{%0,%1,%2,%3},{%4,%5,%6,%7},{%8,%9},{%0,%1,%2,%3};" \
        : "+f"((c)[0]), "+f"((c)[1]), "+f"((c)[2]), "+f"((c)[3]) \
        : "r"((a)[0]), "r"((a)[1]), "r"((a)[2]), "r"((a)[3]), "r"((b)[0]), "r"((b)[1]))

#define LDMX4(r, addr) \
    asm volatile("ldmatrix.sync.aligned.m8n8.x4.shared.b16 {%0,%1,%2,%3}, [%4];" \
        : "=r"((r)[0]), "=r"((r)[1]), "=r"((r)[2]), "=r"((r)[3]) : "r"(addr))

#define STSV2(addr, r0, r1) \
    asm volatile("st.shared.v2.b32 [%0], {%1,%2};" :: "r"(addr), "r"(r0), "r"(r1) : "memory")

extern __shared__ unsigned char smem_raw[];

__global__ __launch_bounds__(128, 2)
void attn_mma_kernel(const float* __restrict__ q, const float* __restrict__ k,
                     const float* __restrict__ v, float* __restrict__ out)
{
    const uint32_t sb   = smem_u32(smem_raw);
    const uint32_t qh_b = sb + SM_QH, ql_b = sb + SM_QL;
    const uint32_t kh_b = sb + SM_KH;
    const uint32_t vt_b = sb + SM_VT, p_b  = sb + SM_P;
    uint32_t* VT = reinterpret_cast<uint32_t*>(smem_raw + SM_VT);
    uint32_t* Pp = reinterpret_cast<uint32_t*>(smem_raw + SM_P);

    const int tid  = threadIdx.x;
    const int lane = tid & 31;
    const int wid  = tid >> 5;           // warp owns rows wid*16 .. wid*16+15
    const int g    = lane >> 2;
    const int tg   = lane & 3;

    const int qt  = (gridDim.x - 1) - blockIdx.x;   // heavy blocks first
    const int hh  = blockIdx.y;
    const int kvh = hh >> 2;
    const int q0  = qt * BM;

    // ---- Q fill (once): split fp16 hi/lo, packed pairs along d ----
    {
        const int m  = tid >> 1;
        const int dh = (tid & 1) * 64;
        const float4* gq = reinterpret_cast<const float4*>(
            q + ((size_t)(q0 + m) * NH + hh) * HD + dh);
        const float sc = QK_SCALE * LOG2E;
        #pragma unroll
        for (int j = 0; j < 16; ++j) {
            float4 val = gq[j];
            uint32_t h0, l0, h1, l1;
            split_pack(val.x * sc, val.y * sc, h0, l0);
            split_pack(val.z * sc, val.w * sc, h1, l1);
            const uint32_t off = (uint32_t)(m * QKSTR + dh / 2 + j * 2) * 4u;
            STSV2(qh_b + off, h0, h1);
            STSV2(ql_b + off, l0, l1);
        }
    }

    // Per-thread rows: hb=0 -> row wid*16+g, hb=1 -> +8
    float m_s[2] = { -INFINITY, -INFINITY };
    float l_s[2] = { 0.f, 0.f };
    float o[16][4];
    #pragma unroll
    for (int nt = 0; nt < 16; ++nt)
        #pragma unroll
        for (int j = 0; j < 4; ++j) o[nt][j] = 0.f;

    for (int kt = 0; kt <= qt; ++kt) {
        __syncthreads();   // prev iter's gemm2 done with K/VT/P

        // ---- K fill: fp16 (hi only), [kv][d-pairs] ----
        {
            const int kv = tid >> 1;
            const int dh = (tid & 1) * 64;
            const float4* gk = reinterpret_cast<const float4*>(
                k + ((size_t)(kt * BN + kv) * NKVH + kvh) * HD + dh);
            #pragma unroll
            for (int j = 0; j < 16; ++j) {
                float4 val = gk[j];
                const uint32_t off = (uint32_t)(kv * QKSTR + dh / 2 + j * 2) * 4u;
                STSV2(kh_b + off, pack_f16x2(val.x, val.y), pack_f16x2(val.z, val.w));
            }
        }
        // ---- V fill: VT[d][p] = f16x2(V[2p][d], V[2p+1][d]) ----
        {
            const int p  = lane;
            const int dh = wid * 32;
            const float4* gv0 = reinterpret_cast<const float4*>(
                v + ((size_t)(kt * BN + 2 * p) * NKVH + kvh) * HD + dh);
            const float4* gv1 = reinterpret_cast<const float4*>(
                v + ((size_t)(kt * BN + 2 * p + 1) * NKVH + kvh) * HD + dh);
            #pragma unroll
            for (int j = 0; j < 8; ++j) {
                float4 a = gv0[j], b = gv1[j];
                const int d = dh + j * 4;
                VT[(d + 0) * VSTR + p] = pack_f16x2(a.x, b.x);
                VT[(d + 1) * VSTR + p] = pack_f16x2(a.y, b.y);
                VT[(d + 2) * VSTR + p] = pack_f16x2(a.z, b.z);
                VT[(d + 3) * VSTR + p] = pack_f16x2(a.w, b.w);
            }
        }
        __syncthreads();

        // ---- gemm1: S = (Qh + Ql) * Kh  (warp: 16x64) ----
        float c1[8][4];
        #pragma unroll
        for (int nt = 0; nt < 8; ++nt)
            #pragma unroll
            for (int j = 0; j < 4; ++j) c1[nt][j] = 0.f;

        #pragma unroll
        for (int kc = 0; kc < 8; ++kc) {
            uint32_t aH[4], aL[4], bH[8][2];
            const uint32_t offA = (uint32_t)((wid * 16 + (lane & 15)) * QKSTR
                                             + kc * 8 + (lane >> 4) * 4) * 4u;
            LDMX4(aH, qh_b + offA);
            LDMX4(aL, ql_b + offA);
            #pragma unroll
            for (int t = 0; t < 4; ++t) {
                const uint32_t offB = (uint32_t)((t * 16 + ((lane >> 4) & 1) * 8 + (lane & 7)) * QKSTR
                                                 + kc * 8 + ((lane >> 3) & 1) * 4) * 4u;
                uint32_t rh[4];
                LDMX4(rh, kh_b + offB);
                bH[2*t][0] = rh[0]; bH[2*t][1] = rh[1]; bH[2*t+1][0] = rh[2]; bH[2*t+1][1] = rh[3];
            }
            #pragma unroll
            for (int nt = 0; nt < 8; ++nt) {
                MMA_F16(c1[nt], aH, bH[nt]);
                MMA_F16(c1[nt], aL, bH[nt]);
            }
        }

        // ---- mask (diag tile) + online softmax (rows warp-local) ----
        const bool diag = (kt == qt);
        #pragma unroll
        for (int hb = 0; hb < 2; ++hb) {
            const int qi = q0 + wid * 16 + g + hb * 8;
            if (diag) {
                #pragma unroll
                for (int nt = 0; nt < 8; ++nt) {
                    const int kj = kt * BN + nt * 8 + 2 * tg;
                    if (kj + 0 > qi) c1[nt][hb * 2 + 0] = -INFINITY;
                    if (kj + 1 > qi) c1[nt][hb * 2 + 1] = -INFINITY;
                }
            }
            float mx = -INFINITY;
            #pragma unroll
            for (int nt = 0; nt < 8; ++nt)
                mx = fmaxf(mx, fmaxf(c1[nt][hb * 2], c1[nt][hb * 2 + 1]));
            mx = fmaxf(mx, __shfl_xor_sync(0xffffffffu, mx, 1));
            mx = fmaxf(mx, __shfl_xor_sync(0xffffffffu, mx, 2));

            const float m_new = fmaxf(m_s[hb], mx);   // finite on diag: col<=row exists
            const float alpha = ex2(m_s[hb] - m_new);
            m_s[hb] = m_new;

            float rs = 0.f;
            #pragma unroll
            for (int nt = 0; nt < 8; ++nt) {
                float p0 = ex2(c1[nt][hb * 2 + 0] - m_new);
                float p1 = ex2(c1[nt][hb * 2 + 1] - m_new);
                c1[nt][hb * 2 + 0] = p0;
                c1[nt][hb * 2 + 1] = p1;
                rs += p0 + p1;
            }
            rs += __shfl_xor_sync(0xffffffffu, rs, 1);
            rs += __shfl_xor_sync(0xffffffffu, rs, 2);
            l_s[hb] = l_s[hb] * alpha + rs;

            #pragma unroll
            for (int nt = 0; nt < 16; ++nt) {
                o[nt][hb * 2 + 0] *= alpha;
                o[nt][hb * 2 + 1] *= alpha;
            }
        }

        // ---- P -> smem (fp16x2), warp-local rows ----
        {
            const int rl = wid * 16 + g;
            #pragma unroll
            for (int nt = 0; nt < 8; ++nt) {
                const int wc = nt * 4 + tg;
                Pp[(rl + 0) * PSTR + wc] = pack_f16x2(c1[nt][0], c1[nt][1]);
                Pp[(rl + 8) * PSTR + wc] = pack_f16x2(c1[nt][2], c1[nt][3]);
            }
        }
        __syncwarp();   // P rows are warp-local; warp-scope sync suffices

        // ---- gemm2: O += P V (fp16) ----
        uint32_t aP[4][4];
        #pragma unroll
        for (int kc = 0; kc < 4; ++kc) {
            const uint32_t addr = p_b +
                (uint32_t)((wid * 16 + (lane & 15)) * PSTR + (lane >> 4) * 4 + kc * 8) * 4u;
            LDMX4(aP[kc], addr);
        }
        #pragma unroll
        for (int kc = 0; kc < 4; ++kc) {
            #pragma unroll
            for (int t = 0; t < 8; ++t) {
                const uint32_t offV = (uint32_t)((t * 16 + ((lane >> 4) & 1) * 8 + (lane & 7)) * VSTR
                                                 + kc * 8 + ((lane >> 3) & 1) * 4) * 4u;
                uint32_t rv[4];
                LDMX4(rv, vt_b + offV);
                uint32_t b0[2] = { rv[0], rv[1] }, b1[2] = { rv[2], rv[3] };
                MMA_F16(o[2 * t + 0], aP[kc], b0);
                MMA_F16(o[2 * t + 1], aP[kc], b1);
            }
        }
    }

    // ---- Epilogue: normalize, store ----
    #pragma unroll
    for (int hb = 0; hb < 2; ++hb) {
        const float inv = 1.f / l_s[hb];
        const int grow = q0 + wid * 16 + g + hb * 8;
        float* obase = out + ((size_t)grow * NH + hh) * HD + 2 * tg;
        #pragma unroll
        for (int nt = 0; nt < 16; ++nt) {
            float2 val = make_float2(o[nt][hb * 2 + 0] * inv,
                                     o[nt][hb * 2 + 1] * inv);
            *reinterpret_cast<float2*>(obase + nt * 8) = val;
        }
    }
}

extern "C" void kernel_launch(void* const* d_in, const int* in_sizes, int n_in,
                              void* d_out, int out_size)
{
    const float* q = (const float*)d_in[0];
    const float* k = (const float*)d_in[1];
    const float* v = (const float*)d_in[2];
    float* out = (float*)d_out;

    const int seq = in_sizes[0] / (NH * HD);

    cudaFuncSetAttribute(attn_mma_kernel,
                         cudaFuncAttributeMaxDynamicSharedMemorySize, SMEM_BYTES);

    dim3 grid(seq / BM, NH);
    attn_mma_kernel<<<grid, 128, SMEM_BYTES>>>(q, k, v, out);
}

// round 9
// speedup vs baseline: 3.5862x; 1.0569x over previous
#include <cuda_runtime.h>
#include <cuda_fp16.h>
#include <cstdint>
#include <math.h>

// Causal GQA attention prefill, S=2048, H=32, KVH=8, D=128, fp32 I/O.
// Pure fp16 mma.sync (gemm1 + gemm2), double-buffered K/V fills:
// prefetch of tile kt+1 overlaps compute of tile kt; one barrier per iteration.
// 4x1 warp tiling: each warp owns 16 full score rows (warp-local softmax).

#define NH    32
#define NKVH  8
#define HD    128
#define BM    64
#define BN    64
#define QK_SCALE 0.08838834764831845f
#define LOG2E    1.4426950408889634f

// u32-word strides, all == 4 (mod 32): conflict-free ldmatrix row patterns
#define QKSTR 68   // Q/K rows: 64 u32 data + 4 pad
#define VSTR  36   // VT rows: 32 u32 + 4 pad
#define PSTR  36

// byte offsets in dynamic smem
#define SM_Q  0
#define SM_K0 17408
#define SM_K1 34816
#define SM_V0 52224
#define SM_V1 70656
#define SM_P  89088
#define SMEM_BYTES 98304

__device__ __forceinline__ uint32_t smem_u32(const void* p) {
    uint32_t a;
    asm("{ .reg .u64 t; cvta.to.shared.u64 t, %1; cvt.u32.u64 %0, t; }" : "=r"(a) : "l"(p));
    return a;
}
__device__ __forceinline__ float ex2(float x) {
    float r; asm("ex2.approx.f32 %0, %1;" : "=f"(r) : "f"(x)); return r;
}
__device__ __forceinline__ uint32_t pack_f16x2(float lo, float hi) {
    uint32_t r; asm("cvt.rn.f16x2.f32 %0, %1, %2;" : "=r"(r) : "f"(hi), "f"(lo)); return r;
}

#define MMA_F16(c, a, b) \
    asm volatile("mma.sync.aligned.m16n8k16.row.col.f32.f16.f16.f32 " \
                 "{%0,%1,%2,%3},{%4,%5,%6,%7},{%8,%9},{%0,%1,%2,%3};" \
        : "+f"((c)[0]), "+f"((c)[1]), "+f"((c)[2]), "+f"((c)[3]) \
        : "r"((a)[0]), "r"((a)[1]), "r"((a)[2]), "r"((a)[3]), "r"((b)[0]), "r"((b)[1]))

#define LDMX4(r, addr) \
    asm volatile("ldmatrix.sync.aligned.m8n8.x4.shared.b16 {%0,%1,%2,%3}, [%4];" \
        : "=r"((r)[0]), "=r"((r)[1]), "=r"((r)[2]), "=r"((r)[3]) : "r"(addr))

#define STSV2(addr, r0, r1) \
    asm volatile("st.shared.v2.b32 [%0], {%1,%2};" :: "r"(addr), "r"(r0), "r"(r1) : "memory")
#define STS32(addr, r0) \
    asm volatile("st.shared.b32 [%0], %1;" :: "r"(addr), "r"(r0) : "memory")

extern __shared__ unsigned char smem_raw[];

__global__ __launch_bounds__(128, 2)
void attn_mma_kernel(const float* __restrict__ q, const float* __restrict__ k,
                     const float* __restrict__ v, float* __restrict__ out)
{
    const uint32_t sb  = smem_u32(smem_raw);
    const uint32_t q_b = sb + SM_Q;
    const uint32_t k_b[2] = { sb + SM_K0, sb + SM_K1 };
    const uint32_t v_b[2] = { sb + SM_V0, sb + SM_V1 };
    const uint32_t p_b = sb + SM_P;
    uint32_t* Pp = reinterpret_cast<uint32_t*>(smem_raw + SM_P);

    const int tid  = threadIdx.x;
    const int lane = tid & 31;
    const int wid  = tid >> 5;           // warp owns rows wid*16 .. wid*16+15
    const int g    = lane >> 2;
    const int tg   = lane & 3;

    const int qt  = (gridDim.x - 1) - blockIdx.x;   // heavy blocks first
    const int hh  = blockIdx.y;
    const int kvh = hh >> 2;
    const int q0  = qt * BM;

    // per-thread fill coordinates
    const int f_kv = tid >> 1;            // K fill: row
    const int f_dh = (tid & 1) * 64;      // K fill: d-half
    const int v_p  = lane;                // V fill: kv-pair
    const int v_dh = wid * 32;            // V fill: d-chunk

    // ---- Q fill (once): fp16, packed pairs along d ----
    {
        const float4* gq = reinterpret_cast<const float4*>(
            q + ((size_t)(q0 + f_kv) * NH + hh) * HD + f_dh);
        const float sc = QK_SCALE * LOG2E;
        #pragma unroll
        for (int j = 0; j < 16; ++j) {
            float4 val = gq[j];
            const uint32_t off = (uint32_t)(f_kv * QKSTR + f_dh / 2 + j * 2) * 4u;
            STSV2(q_b + off, pack_f16x2(val.x * sc, val.y * sc),
                             pack_f16x2(val.z * sc, val.w * sc));
        }
    }
    // ---- initial K/V fill (tile 0 -> buffer 0) ----
    {
        const float4* gk = reinterpret_cast<const float4*>(
            k + ((size_t)f_kv * NKVH + kvh) * HD + f_dh);
        #pragma unroll
        for (int j = 0; j < 16; ++j) {
            float4 val = gk[j];
            const uint32_t off = (uint32_t)(f_kv * QKSTR + f_dh / 2 + j * 2) * 4u;
            STSV2(k_b[0] + off, pack_f16x2(val.x, val.y), pack_f16x2(val.z, val.w));
        }
        const float4* gv0 = reinterpret_cast<const float4*>(
            v + ((size_t)(2 * v_p) * NKVH + kvh) * HD + v_dh);
        const float4* gv1 = reinterpret_cast<const float4*>(
            v + ((size_t)(2 * v_p + 1) * NKVH + kvh) * HD + v_dh);
        #pragma unroll
        for (int j = 0; j < 8; ++j) {
            float4 a = gv0[j], b = gv1[j];
            const int d = v_dh + j * 4;
            STS32(v_b[0] + (uint32_t)((d + 0) * VSTR + v_p) * 4u, pack_f16x2(a.x, b.x));
            STS32(v_b[0] + (uint32_t)((d + 1) * VSTR + v_p) * 4u, pack_f16x2(a.y, b.y));
            STS32(v_b[0] + (uint32_t)((d + 2) * VSTR + v_p) * 4u, pack_f16x2(a.z, b.z));
            STS32(v_b[0] + (uint32_t)((d + 3) * VSTR + v_p) * 4u, pack_f16x2(a.w, b.w));
        }
    }
    __syncthreads();

    // Per-thread rows: hb=0 -> row wid*16+g, hb=1 -> +8
    float m_s[2] = { -INFINITY, -INFINITY };
    float l_s[2] = { 0.f, 0.f };
    float o[16][4];
    #pragma unroll
    for (int nt = 0; nt < 16; ++nt)
        #pragma unroll
        for (int j = 0; j < 4; ++j) o[nt][j] = 0.f;

    for (int kt = 0; kt <= qt; ++kt) {
        // ---- prefetch K/V for tile kt+1 into the alternate buffer ----
        // Target buffer's readers all passed the barrier at end of iter kt-1.
        if (kt < qt) {
            const int ktn = kt + 1;
            const uint32_t kb = k_b[ktn & 1], vb = v_b[ktn & 1];
            const float4* gk = reinterpret_cast<const float4*>(
                k + ((size_t)(ktn * BN + f_kv) * NKVH + kvh) * HD + f_dh);
            #pragma unroll
            for (int j = 0; j < 16; ++j) {
                float4 val = gk[j];
                const uint32_t off = (uint32_t)(f_kv * QKSTR + f_dh / 2 + j * 2) * 4u;
                STSV2(kb + off, pack_f16x2(val.x, val.y), pack_f16x2(val.z, val.w));
            }
            const float4* gv0 = reinterpret_cast<const float4*>(
                v + ((size_t)(ktn * BN + 2 * v_p) * NKVH + kvh) * HD + v_dh);
            const float4* gv1 = reinterpret_cast<const float4*>(
                v + ((size_t)(ktn * BN + 2 * v_p + 1) * NKVH + kvh) * HD + v_dh);
            #pragma unroll
            for (int j = 0; j < 8; ++j) {
                float4 a = gv0[j], b = gv1[j];
                const int d = v_dh + j * 4;
                STS32(vb + (uint32_t)((d + 0) * VSTR + v_p) * 4u, pack_f16x2(a.x, b.x));
                STS32(vb + (uint32_t)((d + 1) * VSTR + v_p) * 4u, pack_f16x2(a.y, b.y));
                STS32(vb + (uint32_t)((d + 2) * VSTR + v_p) * 4u, pack_f16x2(a.z, b.z));
                STS32(vb + (uint32_t)((d + 3) * VSTR + v_p) * 4u, pack_f16x2(a.w, b.w));
            }
        }

        const uint32_t kb_cur = k_b[kt & 1];
        const uint32_t vb_cur = v_b[kt & 1];

        // ---- gemm1: S = Q * K^T (fp16, warp: 16x64) ----
        float c1[8][4];
        #pragma unroll
        for (int nt = 0; nt < 8; ++nt)
            #pragma unroll
            for (int j = 0; j < 4; ++j) c1[nt][j] = 0.f;

        #pragma unroll
        for (int kc = 0; kc < 8; ++kc) {
            uint32_t aH[4], bH[8][2];
            const uint32_t offA = (uint32_t)((wid * 16 + (lane & 15)) * QKSTR
                                             + kc * 8 + (lane >> 4) * 4) * 4u;
            LDMX4(aH, q_b + offA);
            #pragma unroll
            for (int t = 0; t < 4; ++t) {
                const uint32_t offB = (uint32_t)((t * 16 + ((lane >> 4) & 1) * 8 + (lane & 7)) * QKSTR
                                                 + kc * 8 + ((lane >> 3) & 1) * 4) * 4u;
                uint32_t rh[4];
                LDMX4(rh, kb_cur + offB);
                bH[2*t][0] = rh[0]; bH[2*t][1] = rh[1]; bH[2*t+1][0] = rh[2]; bH[2*t+1][1] = rh[3];
            }
            #pragma unroll
            for (int nt = 0; nt < 8; ++nt)
                MMA_F16(c1[nt], aH, bH[nt]);
        }

        // ---- mask (diag tile) + online softmax (rows warp-local) ----
        const bool diag = (kt == qt);
        #pragma unroll
        for (int hb = 0; hb < 2; ++hb) {
            const int qi = q0 + wid * 16 + g + hb * 8;
            if (diag) {
                #pragma unroll
                for (int nt = 0; nt < 8; ++nt) {
                    const int kj = kt * BN + nt * 8 + 2 * tg;
                    if (kj + 0 > qi) c1[nt][hb * 2 + 0] = -INFINITY;
                    if (kj + 1 > qi) c1[nt][hb * 2 + 1] = -INFINITY;
                }
            }
            float mx = -INFINITY;
            #pragma unroll
            for (int nt = 0; nt < 8; ++nt)
                mx = fmaxf(mx, fmaxf(c1[nt][hb * 2], c1[nt][hb * 2 + 1]));
            mx = fmaxf(mx, __shfl_xor_sync(0xffffffffu, mx, 1));
            mx = fmaxf(mx, __shfl_xor_sync(0xffffffffu, mx, 2));

            const float m_new = fmaxf(m_s[hb], mx);   // finite on diag: col<=row exists
            const float alpha = ex2(m_s[hb] - m_new);
            m_s[hb] = m_new;

            float rs = 0.f;
            #pragma unroll
            for (int nt = 0; nt < 8; ++nt) {
                float p0 = ex2(c1[nt][hb * 2 + 0] - m_new);
                float p1 = ex2(c1[nt][hb * 2 + 1] - m_new);
                c1[nt][hb * 2 + 0] = p0;
                c1[nt][hb * 2 + 1] = p1;
                rs += p0 + p1;
            }
            rs += __shfl_xor_sync(0xffffffffu, rs, 1);
            rs += __shfl_xor_sync(0xffffffffu, rs, 2);
            l_s[hb] = l_s[hb] * alpha + rs;

            #pragma unroll
            for (int nt = 0; nt < 16; ++nt) {
                o[nt][hb * 2 + 0] *= alpha;
                o[nt][hb * 2 + 1] *= alpha;
            }
        }

        // ---- P -> smem (fp16x2), warp-local rows ----
        {
            const int rl = wid * 16 + g;
            #pragma unroll
            for (int nt = 0; nt < 8; ++nt) {
                const int wc = nt * 4 + tg;
                Pp[(rl + 0) * PSTR + wc] = pack_f16x2(c1[nt][0], c1[nt][1]);
                Pp[(rl + 8) * PSTR + wc] = pack_f16x2(c1[nt][2], c1[nt][3]);
            }
        }
        __syncwarp();   // P rows are warp-local

        // ---- gemm2: O += P V (fp16) ----
        uint32_t aP[4][4];
        #pragma unroll
        for (int kc = 0; kc < 4; ++kc) {
            const uint32_t addr = p_b +
                (uint32_t)((wid * 16 + (lane & 15)) * PSTR + (lane >> 4) * 4 + kc * 8) * 4u;
            LDMX4(aP[kc], addr);
        }
        #pragma unroll
        for (int kc = 0; kc < 4; ++kc) {
            #pragma unroll
            for (int t = 0; t < 8; ++t) {
                const uint32_t offV = (uint32_t)((t * 16 + ((lane >> 4) & 1) * 8 + (lane & 7)) * VSTR
                                                 + kc * 8 + ((lane >> 3) & 1) * 4) * 4u;
                uint32_t rv[4];
                LDMX4(rv, vb_cur + offV);
                uint32_t b0[2] = { rv[0], rv[1] }, b1[2] = { rv[2], rv[3] };
                MMA_F16(o[2 * t + 0], aP[kc], b0);
                MMA_F16(o[2 * t + 1], aP[kc], b1);
            }
        }

        __syncthreads();   // prefetched buffer ready; current buffer reads done
    }

    // ---- Epilogue: normalize, store ----
    #pragma unroll
    for (int hb = 0; hb < 2; ++hb) {
        const float inv = 1.f / l_s[hb];
        const int grow = q0 + wid * 16 + g + hb * 8;
        float* obase = out + ((size_t)grow * NH + hh) * HD + 2 * tg;
        #pragma unroll
        for (int nt = 0; nt < 16; ++nt) {
            float2 val = make_float2(o[nt][hb * 2 + 0] * inv,
                                     o[nt][hb * 2 + 1] * inv);
            *reinterpret_cast<float2*>(obase + nt * 8) = val;
        }
    }
}

extern "C" void kernel_launch(void* const* d_in, const int* in_sizes, int n_in,
                              void* d_out, int out_size)
{
    const float* q = (const float*)d_in[0];
    const float* k = (const float*)d_in[1];
    const float* v = (const float*)d_in[2];
    float* out = (float*)d_out;

    const int seq = in_sizes[0] / (NH * HD);

    cudaFuncSetAttribute(attn_mma_kernel,
                         cudaFuncAttributeMaxDynamicSharedMemorySize, SMEM_BYTES);

    dim3 grid(seq / BM, NH);
    attn_mma_kernel<<<grid, 128, SMEM_BYTES>>>(q, k, v, out);
}

// round 10
// speedup vs baseline: 5.1138x; 1.4260x over previous
#include <cuda_runtime.h>
#include <cuda_fp16.h>
#include <cstdint>
#include <math.h>

// Causal GQA attention prefill, S=2048, H=32, KVH=8, D=128, fp32 I/O.
// Pure fp16 mma.sync. Pre-pass converts K/V to fp16 (V transposed+packed) in
// __device__ scratch so main-kernel fills are raw copies. P stays in registers
// (gemm1 C-frag == gemm2 A-frag layout). 3 CTAs/SM via reg cap + 52KB smem.

#define NH    32
#define NKVH  8
#define HD    128
#define BM    64
#define BN    64
#define SMAX  2048
#define QK_SCALE 0.08838834764831845f
#define LOG2E    1.4426950408889634f

#define QKSTR 68   // Q/K row stride in u32 words (64 data + 4 pad)
#define VSTR  36   // VT row stride in u32 words (32 data + 4 pad)

#define SM_Q  0
#define SM_K  17408
#define SM_V  34816
#define SMEM_BYTES 53248

// fp16 scratch (pre-converted). K: [s][kvh][64 d-pairs]. V: [kvh][kt][d][32 kv-pairs].
__device__ uint32_t Kh_g[SMAX * NKVH * 64];
__device__ uint32_t VT_g[NKVH * (SMAX / BN) * HD * 32];

__device__ __forceinline__ uint32_t smem_u32(const void* p) {
    uint32_t a;
    asm("{ .reg .u64 t; cvta.to.shared.u64 t, %1; cvt.u32.u64 %0, t; }" : "=r"(a) : "l"(p));
    return a;
}
__device__ __forceinline__ float ex2(float x) {
    float r; asm("ex2.approx.f32 %0, %1;" : "=f"(r) : "f"(x)); return r;
}
__device__ __forceinline__ uint32_t pack_f16x2(float lo, float hi) {
    uint32_t r; asm("cvt.rn.f16x2.f32 %0, %1, %2;" : "=r"(r) : "f"(hi), "f"(lo)); return r;
}

#define MMA_F16(c, a, b) \
    asm volatile("mma.sync.aligned.m16n8k16.row.col.f32.f16.f16.f32 " \
                 "{%0,%1,%2,%3},{%4,%5,%6,%7},{%8,%9},{%0,%1,%2,%3};" \
        : "+f"((c)[0]), "+f"((c)[1]), "+f"((c)[2]), "+f"((c)[3]) \
        : "r"((a)[0]), "r"((a)[1]), "r"((a)[2]), "r"((a)[3]), "r"((b)[0]), "r"((b)[1]))

#define LDMX4(r, addr) \
    asm volatile("ldmatrix.sync.aligned.m8n8.x4.shared.b16 {%0,%1,%2,%3}, [%4];" \
        : "=r"((r)[0]), "=r"((r)[1]), "=r"((r)[2]), "=r"((r)[3]) : "r"(addr))

#define STSV2(addr, r0, r1) \
    asm volatile("st.shared.v2.b32 [%0], {%1,%2};" :: "r"(addr), "r"(r0), "r"(r1) : "memory")

// ---- pre-pass 1: K fp32 -> fp16 packed, linear (fully coalesced) ----
__global__ void convert_k_kernel(const float* __restrict__ k, int n_pairs)
{
    int i = blockIdx.x * blockDim.x + threadIdx.x;
    if (i < n_pairs) {
        float2 val = reinterpret_cast<const float2*>(k)[i];
        Kh_g[i] = pack_f16x2(val.x, val.y);
    }
}

// ---- pre-pass 2: V fp32 -> fp16 transposed + kv-pair packed ----
// block = (kt, kvh); VT_g[((kvh*nkt + kt)*HD + d)*32 + p] = f16x2(V[2p][d], V[2p+1][d])
__global__ void convert_v_kernel(const float* __restrict__ v)
{
    __shared__ float vs[64][129];
    const int kt = blockIdx.x, kvh = blockIdx.y, nkt = gridDim.x;
    const int tid = threadIdx.x;

    #pragma unroll
    for (int it = 0; it < 16; ++it) {
        const int idx = tid + it * 128;          // 2048 float4 total
        const int row = idx >> 5, f4 = idx & 31;
        float4 val = *reinterpret_cast<const float4*>(
            v + ((size_t)((kt * 64 + row) * NKVH + kvh)) * HD + f4 * 4);
        vs[row][f4 * 4 + 0] = val.x; vs[row][f4 * 4 + 1] = val.y;
        vs[row][f4 * 4 + 2] = val.z; vs[row][f4 * 4 + 3] = val.w;
    }
    __syncthreads();

    const int d = tid;                            // 0..127
    uint32_t* outp = VT_g + ((size_t)(kvh * nkt + kt) * HD + d) * 32;
    #pragma unroll
    for (int p = 0; p < 32; ++p)
        outp[p] = pack_f16x2(vs[2 * p][d], vs[2 * p + 1][d]);
}

extern __shared__ unsigned char smem_raw[];

__global__ __launch_bounds__(128, 3)
void attn_mma_kernel(const float* __restrict__ q, float* __restrict__ out, int seq)
{
    const uint32_t sb  = smem_u32(smem_raw);
    const uint32_t q_b = sb + SM_Q;
    const uint32_t k_b = sb + SM_K;
    const uint32_t v_b = sb + SM_V;

    const int tid  = threadIdx.x;
    const int lane = tid & 31;
    const int wid  = tid >> 5;           // warp owns rows wid*16 .. wid*16+15
    const int g    = lane >> 2;
    const int tg   = lane & 3;

    const int qt  = (gridDim.x - 1) - blockIdx.x;   // heavy blocks first
    const int hh  = blockIdx.y;
    const int kvh = hh >> 2;
    const int q0  = qt * BM;
    const int nkt = seq >> 6;

    // ---- Q fill (once): fp32 gmem -> fp16 smem, scale*log2e folded ----
    {
        const int m  = tid >> 1;
        const int dh = (tid & 1) * 64;
        const float4* gq = reinterpret_cast<const float4*>(
            q + ((size_t)(q0 + m) * NH + hh) * HD + dh);
        const float sc = QK_SCALE * LOG2E;
        #pragma unroll
        for (int j = 0; j < 16; ++j) {
            float4 val = gq[j];
            const uint32_t off = (uint32_t)(m * QKSTR + dh / 2 + j * 2) * 4u;
            STSV2(q_b + off, pack_f16x2(val.x * sc, val.y * sc),
                             pack_f16x2(val.z * sc, val.w * sc));
        }
    }

    // Per-thread rows: hb=0 -> row wid*16+g, hb=1 -> +8
    float m_s[2] = { -INFINITY, -INFINITY };
    float l_s[2] = { 0.f, 0.f };
    float o[16][4];
    #pragma unroll
    for (int nt = 0; nt < 16; ++nt)
        #pragma unroll
        for (int j = 0; j < 4; ++j) o[nt][j] = 0.f;

    // fill coords
    const int f_kv = tid >> 1;            // K fill row
    const int f_dp = (tid & 1) * 32;      // K fill d-pair offset

    for (int kt = 0; kt <= qt; ++kt) {
        __syncthreads();   // prev iter done reading K/V smem

        // ---- K fill: raw copy Kh_g -> smem [kv][d-pairs] ----
        {
            const uint4* src = reinterpret_cast<const uint4*>(
                Kh_g + ((size_t)(kt * BN + f_kv) * NKVH + kvh) * 64 + f_dp);
            const uint32_t dst = k_b + (uint32_t)(f_kv * QKSTR + f_dp) * 4u;
            #pragma unroll
            for (int j = 0; j < 8; ++j) {
                uint4 t = src[j];
                asm volatile("st.shared.v4.b32 [%0], {%1,%2,%3,%4};"
                    :: "r"(dst + j * 16u), "r"(t.x), "r"(t.y), "r"(t.z), "r"(t.w) : "memory");
            }
        }
        // ---- V fill: raw copy VT_g -> smem [d][kv-pairs] ----
        {
            const uint4* src = reinterpret_cast<const uint4*>(
                VT_g + ((size_t)(kvh * nkt + kt) * HD + tid) * 32);
            const uint32_t dst = v_b + (uint32_t)(tid * VSTR) * 4u;
            #pragma unroll
            for (int j = 0; j < 8; ++j) {
                uint4 t = src[j];
                asm volatile("st.shared.v4.b32 [%0], {%1,%2,%3,%4};"
                    :: "r"(dst + j * 16u), "r"(t.x), "r"(t.y), "r"(t.z), "r"(t.w) : "memory");
            }
        }
        __syncthreads();

        // ---- gemm1: S = Q * K^T (fp16, warp: 16x64) ----
        float c1[8][4];
        #pragma unroll
        for (int nt = 0; nt < 8; ++nt)
            #pragma unroll
            for (int j = 0; j < 4; ++j) c1[nt][j] = 0.f;

        #pragma unroll
        for (int kc = 0; kc < 8; ++kc) {
            uint32_t aH[4], bH[8][2];
            const uint32_t offA = (uint32_t)((wid * 16 + (lane & 15)) * QKSTR
                                             + kc * 8 + (lane >> 4) * 4) * 4u;
            LDMX4(aH, q_b + offA);
            #pragma unroll
            for (int t = 0; t < 4; ++t) {
                const uint32_t offB = (uint32_t)((t * 16 + ((lane >> 4) & 1) * 8 + (lane & 7)) * QKSTR
                                                 + kc * 8 + ((lane >> 3) & 1) * 4) * 4u;
                uint32_t rh[4];
                LDMX4(rh, k_b + offB);
                bH[2*t][0] = rh[0]; bH[2*t][1] = rh[1]; bH[2*t+1][0] = rh[2]; bH[2*t+1][1] = rh[3];
            }
            #pragma unroll
            for (int nt = 0; nt < 8; ++nt)
                MMA_F16(c1[nt], aH, bH[nt]);
        }

        // ---- mask (diag tile) + online softmax (rows warp-local) ----
        const bool diag = (kt == qt);
        #pragma unroll
        for (int hb = 0; hb < 2; ++hb) {
            const int qi = q0 + wid * 16 + g + hb * 8;
            if (diag) {
                #pragma unroll
                for (int nt = 0; nt < 8; ++nt) {
                    const int kj = kt * BN + nt * 8 + 2 * tg;
                    if (kj + 0 > qi) c1[nt][hb * 2 + 0] = -INFINITY;
                    if (kj + 1 > qi) c1[nt][hb * 2 + 1] = -INFINITY;
                }
            }
            float mx = -INFINITY;
            #pragma unroll
            for (int nt = 0; nt < 8; ++nt)
                mx = fmaxf(mx, fmaxf(c1[nt][hb * 2], c1[nt][hb * 2 + 1]));
            mx = fmaxf(mx, __shfl_xor_sync(0xffffffffu, mx, 1));
            mx = fmaxf(mx, __shfl_xor_sync(0xffffffffu, mx, 2));

            const float m_new = fmaxf(m_s[hb], mx);   // finite on diag
            const float alpha = ex2(m_s[hb] - m_new);
            m_s[hb] = m_new;

            float rs = 0.f;
            #pragma unroll
            for (int nt = 0; nt < 8; ++nt) {
                float p0 = ex2(c1[nt][hb * 2 + 0] - m_new);
                float p1 = ex2(c1[nt][hb * 2 + 1] - m_new);
                c1[nt][hb * 2 + 0] = p0;
                c1[nt][hb * 2 + 1] = p1;
                rs += p0 + p1;
            }
            rs += __shfl_xor_sync(0xffffffffu, rs, 1);
            rs += __shfl_xor_sync(0xffffffffu, rs, 2);
            l_s[hb] = l_s[hb] * alpha + rs;

            #pragma unroll
            for (int nt = 0; nt < 16; ++nt) {
                o[nt][hb * 2 + 0] *= alpha;
                o[nt][hb * 2 + 1] *= alpha;
            }
        }

        // ---- gemm2: O += P V. P packed from c1 registers (no smem) ----
        #pragma unroll
        for (int kc = 0; kc < 4; ++kc) {
            uint32_t aP[4];
            aP[0] = pack_f16x2(c1[2*kc+0][0], c1[2*kc+0][1]);
            aP[1] = pack_f16x2(c1[2*kc+0][2], c1[2*kc+0][3]);
            aP[2] = pack_f16x2(c1[2*kc+1][0], c1[2*kc+1][1]);
            aP[3] = pack_f16x2(c1[2*kc+1][2], c1[2*kc+1][3]);
            #pragma unroll
            for (int t = 0; t < 8; ++t) {
                const uint32_t offV = (uint32_t)((t * 16 + ((lane >> 4) & 1) * 8 + (lane & 7)) * VSTR
                                                 + kc * 8 + ((lane >> 3) & 1) * 4) * 4u;
                uint32_t rv[4];
                LDMX4(rv, v_b + offV);
                uint32_t b0[2] = { rv[0], rv[1] }, b1[2] = { rv[2], rv[3] };
                MMA_F16(o[2 * t + 0], aP, b0);
                MMA_F16(o[2 * t + 1], aP, b1);
            }
        }
    }

    // ---- Epilogue: normalize, store ----
    #pragma unroll
    for (int hb = 0; hb < 2; ++hb) {
        const float inv = 1.f / l_s[hb];
        const int grow = q0 + wid * 16 + g + hb * 8;
        float* obase = out + ((size_t)grow * NH + hh) * HD + 2 * tg;
        #pragma unroll
        for (int nt = 0; nt < 16; ++nt) {
            float2 val = make_float2(o[nt][hb * 2 + 0] * inv,
                                     o[nt][hb * 2 + 1] * inv);
            *reinterpret_cast<float2*>(obase + nt * 8) = val;
        }
    }
}

extern "C" void kernel_launch(void* const* d_in, const int* in_sizes, int n_in,
                              void* d_out, int out_size)
{
    const float* q = (const float*)d_in[0];
    const float* k = (const float*)d_in[1];
    const float* v = (const float*)d_in[2];
    float* out = (float*)d_out;

    const int seq = in_sizes[0] / (NH * HD);

    // pre-pass conversions (ordered on the same stream; graph-capturable)
    const int n_pairs = seq * NKVH * 64;
    convert_k_kernel<<<(n_pairs + 255) / 256, 256>>>(k, n_pairs);
    convert_v_kernel<<<dim3(seq / BN, NKVH), 128>>>(v);

    cudaFuncSetAttribute(attn_mma_kernel,
                         cudaFuncAttributeMaxDynamicSharedMemorySize, SMEM_BYTES);

    dim3 grid(seq / BM, NH);
    attn_mma_kernel<<<grid, 128, SMEM_BYTES>>>(q, out, seq);
}

// round 11
// speedup vs baseline: 6.6994x; 1.3101x over previous
#include <cuda_runtime.h>
#include <cuda_fp16.h>
#include <cstdint>
#include <math.h>

// Causal GQA attention prefill, S=2048, H=32, KVH=8, D=128, fp32 I/O.
// Pure fp16 mma.sync. Pre-pass converts K/V to fp16 (V transposed+packed).
// BM=128: each of 4 warps owns 32 rows -> K/V B-fragments amortized over 2x rows.
// P stays in registers (gemm1 C-frag == gemm2 A-frag layout).

#define NH    32
#define NKVH  8
#define HD    128
#define BM    128
#define BN    64
#define SMAX  2048
#define QK_SCALE 0.08838834764831845f
#define LOG2E    1.4426950408889634f

#define QKSTR 68   // Q/K row stride in u32 words (64 data + 4 pad)
#define VSTR  36   // VT row stride in u32 words (32 data + 4 pad)

#define SM_Q  0                       // Q [128][68] u32 = 34816 B
#define SM_K  34816                   // K [64][68]  u32 = 17408 B
#define SM_V  52224                   // V [128][36] u32 = 18432 B
#define SMEM_BYTES 70656

// fp16 scratch (pre-converted). K: [s][kvh][64 d-pairs]. V: [kvh][kt][d][32 kv-pairs].
__device__ uint32_t Kh_g[SMAX * NKVH * 64];
__device__ uint32_t VT_g[NKVH * (SMAX / BN) * HD * 32];

__device__ __forceinline__ uint32_t smem_u32(const void* p) {
    uint32_t a;
    asm("{ .reg .u64 t; cvta.to.shared.u64 t, %1; cvt.u32.u64 %0, t; }" : "=r"(a) : "l"(p));
    return a;
}
__device__ __forceinline__ float ex2(float x) {
    float r; asm("ex2.approx.f32 %0, %1;" : "=f"(r) : "f"(x)); return r;
}
__device__ __forceinline__ uint32_t pack_f16x2(float lo, float hi) {
    uint32_t r; asm("cvt.rn.f16x2.f32 %0, %1, %2;" : "=r"(r) : "f"(hi), "f"(lo)); return r;
}

#define MMA_F16(c, a, b) \
    asm volatile("mma.sync.aligned.m16n8k16.row.col.f32.f16.f16.f32 " \
                 "{%0,%1,%2,%3},{%4,%5,%6,%7},{%8,%9},{%0,%1,%2,%3};" \
        : "+f"((c)[0]), "+f"((c)[1]), "+f"((c)[2]), "+f"((c)[3]) \
        : "r"((a)[0]), "r"((a)[1]), "r"((a)[2]), "r"((a)[3]), "r"((b)[0]), "r"((b)[1]))

#define LDMX4(r, addr) \
    asm volatile("ldmatrix.sync.aligned.m8n8.x4.shared.b16 {%0,%1,%2,%3}, [%4];" \
        : "=r"((r)[0]), "=r"((r)[1]), "=r"((r)[2]), "=r"((r)[3]) : "r"(addr))

#define STSV2(addr, r0, r1) \
    asm volatile("st.shared.v2.b32 [%0], {%1,%2};" :: "r"(addr), "r"(r0), "r"(r1) : "memory")
#define STSV4(addr, t) \
    asm volatile("st.shared.v4.b32 [%0], {%1,%2,%3,%4};" \
        :: "r"(addr), "r"((t).x), "r"((t).y), "r"((t).z), "r"((t).w) : "memory")

// ---- pre-pass 1: K fp32 -> fp16 packed, linear (fully coalesced) ----
__global__ void convert_k_kernel(const float* __restrict__ k, int n_pairs)
{
    int i = blockIdx.x * blockDim.x + threadIdx.x;
    if (i < n_pairs) {
        float2 val = reinterpret_cast<const float2*>(k)[i];
        Kh_g[i] = pack_f16x2(val.x, val.y);
    }
}

// ---- pre-pass 2: V fp32 -> fp16 transposed + kv-pair packed ----
__global__ void convert_v_kernel(const float* __restrict__ v)
{
    __shared__ float vs[64][129];
    const int kt = blockIdx.x, kvh = blockIdx.y, nkt = gridDim.x;
    const int tid = threadIdx.x;

    #pragma unroll
    for (int it = 0; it < 16; ++it) {
        const int idx = tid + it * 128;
        const int row = idx >> 5, f4 = idx & 31;
        float4 val = *reinterpret_cast<const float4*>(
            v + ((size_t)((kt * 64 + row) * NKVH + kvh)) * HD + f4 * 4);
        vs[row][f4 * 4 + 0] = val.x; vs[row][f4 * 4 + 1] = val.y;
        vs[row][f4 * 4 + 2] = val.z; vs[row][f4 * 4 + 3] = val.w;
    }
    __syncthreads();

    const int d = tid;
    uint32_t* outp = VT_g + ((size_t)(kvh * nkt + kt) * HD + d) * 32;
    #pragma unroll
    for (int p = 0; p < 32; ++p)
        outp[p] = pack_f16x2(vs[2 * p][d], vs[2 * p + 1][d]);
}

extern __shared__ unsigned char smem_raw[];

__global__ __launch_bounds__(128, 2)
void attn_mma_kernel(const float* __restrict__ q, float* __restrict__ out, int seq)
{
    const uint32_t sb  = smem_u32(smem_raw);
    const uint32_t q_b = sb + SM_Q;
    const uint32_t k_b = sb + SM_K;
    const uint32_t v_b = sb + SM_V;

    const int tid  = threadIdx.x;
    const int lane = tid & 31;
    const int wid  = tid >> 5;           // warp owns rows wid*32 .. wid*32+31
    const int g    = lane >> 2;
    const int tg   = lane & 3;

    const int qt  = (gridDim.x - 1) - blockIdx.x;   // heavy blocks first
    const int hh  = blockIdx.y;
    const int kvh = hh >> 2;
    const int q0  = qt * BM;
    const int nkt = seq >> 6;            // 64-wide kv tiles
    const int nkt_this = (qt + 1) * (BM / BN);  // kv tiles needed: 2*(qt+1)

    // ---- Q fill (once): fp32 gmem -> fp16 smem, scale*log2e folded ----
    {
        const float4* gq = reinterpret_cast<const float4*>(
            q + ((size_t)(q0 + tid) * NH + hh) * HD);
        const float sc = QK_SCALE * LOG2E;
        #pragma unroll
        for (int j = 0; j < 32; ++j) {
            float4 val = gq[j];
            const uint32_t off = (uint32_t)(tid * QKSTR + j * 2) * 4u;
            STSV2(q_b + off, pack_f16x2(val.x * sc, val.y * sc),
                             pack_f16x2(val.z * sc, val.w * sc));
        }
    }

    // Per-thread rows: mt in {0,1}, hb in {0,1} -> row wid*32 + mt*16 + g + hb*8
    float m_s[2][2] = { { -INFINITY, -INFINITY }, { -INFINITY, -INFINITY } };
    float l_s[2][2] = { { 0.f, 0.f }, { 0.f, 0.f } };
    float o[2][16][4];
    #pragma unroll
    for (int mt = 0; mt < 2; ++mt)
        #pragma unroll
        for (int nt = 0; nt < 16; ++nt)
            #pragma unroll
            for (int j = 0; j < 4; ++j) o[mt][nt][j] = 0.f;

    // fill coords
    const int f_kv = tid >> 1;
    const int f_dp = (tid & 1) * 32;

    for (int kt = 0; kt < nkt_this; ++kt) {
        __syncthreads();   // prev iter done reading K/V smem

        // ---- K fill: raw copy Kh_g -> smem [kv][d-pairs] ----
        {
            const uint4* src = reinterpret_cast<const uint4*>(
                Kh_g + ((size_t)(kt * BN + f_kv) * NKVH + kvh) * 64 + f_dp);
            const uint32_t dst = k_b + (uint32_t)(f_kv * QKSTR + f_dp) * 4u;
            #pragma unroll
            for (int j = 0; j < 8; ++j) { uint4 t = src[j]; STSV4(dst + j * 16u, t); }
        }
        // ---- V fill: raw copy VT_g -> smem [d][kv-pairs] ----
        {
            const uint4* src = reinterpret_cast<const uint4*>(
                VT_g + ((size_t)(kvh * nkt + kt) * HD + tid) * 32);
            const uint32_t dst = v_b + (uint32_t)(tid * VSTR) * 4u;
            #pragma unroll
            for (int j = 0; j < 8; ++j) { uint4 t = src[j]; STSV4(dst + j * 16u, t); }
        }
        __syncthreads();

        // ---- gemm1: S = Q * K^T (fp16, warp: 32x64) ----
        float c1[2][8][4];
        #pragma unroll
        for (int mt = 0; mt < 2; ++mt)
            #pragma unroll
            for (int nt = 0; nt < 8; ++nt)
                #pragma unroll
                for (int j = 0; j < 4; ++j) c1[mt][nt][j] = 0.f;

        #pragma unroll
        for (int kc = 0; kc < 8; ++kc) {
            uint32_t aH[2][4], bH[8][2];
            #pragma unroll
            for (int mt = 0; mt < 2; ++mt) {
                const uint32_t offA = (uint32_t)((wid * 32 + mt * 16 + (lane & 15)) * QKSTR
                                                 + kc * 8 + (lane >> 4) * 4) * 4u;
                LDMX4(aH[mt], q_b + offA);
            }
            #pragma unroll
            for (int t = 0; t < 4; ++t) {
                const uint32_t offB = (uint32_t)((t * 16 + ((lane >> 4) & 1) * 8 + (lane & 7)) * QKSTR
                                                 + kc * 8 + ((lane >> 3) & 1) * 4) * 4u;
                uint32_t rh[4];
                LDMX4(rh, k_b + offB);
                bH[2*t][0] = rh[0]; bH[2*t][1] = rh[1]; bH[2*t+1][0] = rh[2]; bH[2*t+1][1] = rh[3];
            }
            #pragma unroll
            for (int mt = 0; mt < 2; ++mt)
                #pragma unroll
                for (int nt = 0; nt < 8; ++nt)
                    MMA_F16(c1[mt][nt], aH[mt], bH[nt]);
        }

        // ---- mask (partial tiles) + online softmax (rows warp-local) ----
        // Tile kt covers kv cols [kt*64, kt*64+64). Rows q0..q0+127.
        // Masking needed when kt*64 + 63 > q0 + row  (only the last tiles).
        const bool need_mask = (kt * BN + BN - 1) > (q0 + wid * 32);
        #pragma unroll
        for (int mt = 0; mt < 2; ++mt) {
            #pragma unroll
            for (int hb = 0; hb < 2; ++hb) {
                const int qi = q0 + wid * 32 + mt * 16 + g + hb * 8;
                if (need_mask) {
                    #pragma unroll
                    for (int nt = 0; nt < 8; ++nt) {
                        const int kj = kt * BN + nt * 8 + 2 * tg;
                        if (kj + 0 > qi) c1[mt][nt][hb * 2 + 0] = -INFINITY;
                        if (kj + 1 > qi) c1[mt][nt][hb * 2 + 1] = -INFINITY;
                    }
                }
                float mx = -INFINITY;
                #pragma unroll
                for (int nt = 0; nt < 8; ++nt)
                    mx = fmaxf(mx, fmaxf(c1[mt][nt][hb * 2], c1[mt][nt][hb * 2 + 1]));
                mx = fmaxf(mx, __shfl_xor_sync(0xffffffffu, mx, 1));
                mx = fmaxf(mx, __shfl_xor_sync(0xffffffffu, mx, 2));

                const float m_new = fmaxf(m_s[mt][hb], mx);   // finite: col<=row exists
                const float alpha = ex2(m_s[mt][hb] - m_new);
                m_s[mt][hb] = m_new;

                float rs = 0.f;
                #pragma unroll
                for (int nt = 0; nt < 8; ++nt) {
                    float p0 = ex2(c1[mt][nt][hb * 2 + 0] - m_new);
                    float p1 = ex2(c1[mt][nt][hb * 2 + 1] - m_new);
                    c1[mt][nt][hb * 2 + 0] = p0;
                    c1[mt][nt][hb * 2 + 1] = p1;
                    rs += p0 + p1;
                }
                rs += __shfl_xor_sync(0xffffffffu, rs, 1);
                rs += __shfl_xor_sync(0xffffffffu, rs, 2);
                l_s[mt][hb] = l_s[mt][hb] * alpha + rs;

                #pragma unroll
                for (int nt = 0; nt < 16; ++nt) {
                    o[mt][nt][hb * 2 + 0] *= alpha;
                    o[mt][nt][hb * 2 + 1] *= alpha;
                }
            }
        }

        // ---- gemm2: O += P V. P packed from c1 registers; V frags shared by mt ----
        #pragma unroll
        for (int kc = 0; kc < 4; ++kc) {
            uint32_t aP[2][4];
            #pragma unroll
            for (int mt = 0; mt < 2; ++mt) {
                aP[mt][0] = pack_f16x2(c1[mt][2*kc+0][0], c1[mt][2*kc+0][1]);
                aP[mt][1] = pack_f16x2(c1[mt][2*kc+0][2], c1[mt][2*kc+0][3]);
                aP[mt][2] = pack_f16x2(c1[mt][2*kc+1][0], c1[mt][2*kc+1][1]);
                aP[mt][3] = pack_f16x2(c1[mt][2*kc+1][2], c1[mt][2*kc+1][3]);
            }
            #pragma unroll
            for (int t = 0; t < 8; ++t) {
                const uint32_t offV = (uint32_t)((t * 16 + ((lane >> 4) & 1) * 8 + (lane & 7)) * VSTR
                                                 + kc * 8 + ((lane >> 3) & 1) * 4) * 4u;
                uint32_t rv[4];
                LDMX4(rv, v_b + offV);
                uint32_t b0[2] = { rv[0], rv[1] }, b1[2] = { rv[2], rv[3] };
                #pragma unroll
                for (int mt = 0; mt < 2; ++mt) {
                    MMA_F16(o[mt][2 * t + 0], aP[mt], b0);
                    MMA_F16(o[mt][2 * t + 1], aP[mt], b1);
                }
            }
        }
    }

    // ---- Epilogue: normalize, store ----
    #pragma unroll
    for (int mt = 0; mt < 2; ++mt)
        #pragma unroll
        for (int hb = 0; hb < 2; ++hb) {
            const float inv = 1.f / l_s[mt][hb];
            const int grow = q0 + wid * 32 + mt * 16 + g + hb * 8;
            float* obase = out + ((size_t)grow * NH + hh) * HD + 2 * tg;
            #pragma unroll
            for (int nt = 0; nt < 16; ++nt) {
                float2 val = make_float2(o[mt][nt][hb * 2 + 0] * inv,
                                         o[mt][nt][hb * 2 + 1] * inv);
                *reinterpret_cast<float2*>(obase + nt * 8) = val;
            }
        }
}

extern "C" void kernel_launch(void* const* d_in, const int* in_sizes, int n_in,
                              void* d_out, int out_size)
{
    const float* q = (const float*)d_in[0];
    const float* k = (const float*)d_in[1];
    const float* v = (const float*)d_in[2];
    float* out = (float*)d_out;

    const int seq = in_sizes[0] / (NH * HD);

    const int n_pairs = seq * NKVH * 64;
    convert_k_kernel<<<(n_pairs + 255) / 256, 256>>>(k, n_pairs);
    convert_v_kernel<<<dim3(seq / BN, NKVH), 128>>>(v);

    cudaFuncSetAttribute(attn_mma_kernel,
                         cudaFuncAttributeMaxDynamicSharedMemorySize, SMEM_BYTES);

    dim3 grid(seq / BM, NH);
    attn_mma_kernel<<<grid, 128, SMEM_BYTES>>>(q, out, seq);
}

// round 12
// speedup vs baseline: 6.9274x; 1.0340x over previous
#include <cuda_runtime.h>
#include <cuda_fp16.h>
#include <cstdint>
#include <math.h>

// Causal GQA attention prefill, S=2048, H=32, KVH=8, D=128, fp32 I/O.
// Pure fp16 mma.sync. Pre-pass converts K/V to fp16 (V transposed+packed).
// BM=128, 32 rows/warp. P stays in registers. K/V fills are cp.async.cg
// (L1-bypass, no register round-trip) double-buffered: copy of tile kt+1
// overlaps compute of tile kt; one barrier per iteration.

#define NH    32
#define NKVH  8
#define HD    128
#define BM    128
#define BN    64
#define SMAX  2048
#define QK_SCALE 0.08838834764831845f
#define LOG2E    1.4426950408889634f

#define QKSTR 68   // Q/K row stride in u32 words (64 data + 4 pad)
#define VSTR  36   // VT row stride in u32 words (32 data + 4 pad)

#define SM_Q  0                       // Q  [128][68] u32 = 34816 B
#define SM_K0 34816                   // K0 [64][68]  u32 = 17408 B
#define SM_K1 52224                   // K1
#define SM_V0 69632                   // V0 [128][36] u32 = 18432 B
#define SM_V1 88064                   // V1
#define SMEM_BYTES 106496

// fp16 scratch (pre-converted). K: [s][kvh][64 d-pairs]. V: [kvh][kt][d][32 kv-pairs].
__device__ uint32_t Kh_g[SMAX * NKVH * 64];
__device__ uint32_t VT_g[NKVH * (SMAX / BN) * HD * 32];

__device__ __forceinline__ uint32_t smem_u32(const void* p) {
    uint32_t a;
    asm("{ .reg .u64 t; cvta.to.shared.u64 t, %1; cvt.u32.u64 %0, t; }" : "=r"(a) : "l"(p));
    return a;
}
__device__ __forceinline__ float ex2(float x) {
    float r; asm("ex2.approx.f32 %0, %1;" : "=f"(r) : "f"(x)); return r;
}
__device__ __forceinline__ uint32_t pack_f16x2(float lo, float hi) {
    uint32_t r; asm("cvt.rn.f16x2.f32 %0, %1, %2;" : "=r"(r) : "f"(hi), "f"(lo)); return r;
}

#define MMA_F16(c, a, b) \
    asm volatile("mma.sync.aligned.m16n8k16.row.col.f32.f16.f16.f32 " \
                 "{%0,%1,%2,%3},{%4,%5,%6,%7},{%8,%9},{%0,%1,%2,%3};" \
        : "+f"((c)[0]), "+f"((c)[1]), "+f"((c)[2]), "+f"((c)[3]) \
        : "r"((a)[0]), "r"((a)[1]), "r"((a)[2]), "r"((a)[3]), "r"((b)[0]), "r"((b)[1]))

#define LDMX4(r, addr) \
    asm volatile("ldmatrix.sync.aligned.m8n8.x4.shared.b16 {%0,%1,%2,%3}, [%4];" \
        : "=r"((r)[0]), "=r"((r)[1]), "=r"((r)[2]), "=r"((r)[3]) : "r"(addr))

#define STSV2(addr, r0, r1) \
    asm volatile("st.shared.v2.b32 [%0], {%1,%2};" :: "r"(addr), "r"(r0), "r"(r1) : "memory")

#define CPASYNC16(dst, src) \
    asm volatile("cp.async.cg.shared.global [%0], [%1], 16;" :: "r"(dst), "l"(src) : "memory")
#define CPASYNC_COMMIT() asm volatile("cp.async.commit_group;" ::: "memory")
#define CPASYNC_WAIT0()  asm volatile("cp.async.wait_group 0;" ::: "memory")

// ---- pre-pass 1: K fp32 -> fp16 packed, linear (fully coalesced) ----
__global__ void convert_k_kernel(const float* __restrict__ k, int n_pairs)
{
    int i = blockIdx.x * blockDim.x + threadIdx.x;
    if (i < n_pairs) {
        float2 val = reinterpret_cast<const float2*>(k)[i];
        Kh_g[i] = pack_f16x2(val.x, val.y);
    }
}

// ---- pre-pass 2: V fp32 -> fp16 transposed + kv-pair packed ----
__global__ void convert_v_kernel(const float* __restrict__ v)
{
    __shared__ float vs[64][129];
    const int kt = blockIdx.x, kvh = blockIdx.y, nkt = gridDim.x;
    const int tid = threadIdx.x;

    #pragma unroll
    for (int it = 0; it < 16; ++it) {
        const int idx = tid + it * 128;
        const int row = idx >> 5, f4 = idx & 31;
        float4 val = *reinterpret_cast<const float4*>(
            v + ((size_t)((kt * 64 + row) * NKVH + kvh)) * HD + f4 * 4);
        vs[row][f4 * 4 + 0] = val.x; vs[row][f4 * 4 + 1] = val.y;
        vs[row][f4 * 4 + 2] = val.z; vs[row][f4 * 4 + 3] = val.w;
    }
    __syncthreads();

    const int d = tid;
    uint32_t* outp = VT_g + ((size_t)(kvh * nkt + kt) * HD + d) * 32;
    #pragma unroll
    for (int p = 0; p < 32; ++p)
        outp[p] = pack_f16x2(vs[2 * p][d], vs[2 * p + 1][d]);
}

extern __shared__ unsigned char smem_raw[];

__global__ __launch_bounds__(128, 2)
void attn_mma_kernel(const float* __restrict__ q, float* __restrict__ out, int seq)
{
    const uint32_t sb  = smem_u32(smem_raw);
    const uint32_t q_b = sb + SM_Q;
    const uint32_t k_b[2] = { sb + SM_K0, sb + SM_K1 };
    const uint32_t v_b[2] = { sb + SM_V0, sb + SM_V1 };

    const int tid  = threadIdx.x;
    const int lane = tid & 31;
    const int wid  = tid >> 5;           // warp owns rows wid*32 .. wid*32+31
    const int g    = lane >> 2;
    const int tg   = lane & 3;

    const int qt  = (gridDim.x - 1) - blockIdx.x;   // heavy blocks first
    const int hh  = blockIdx.y;
    const int kvh = hh >> 2;
    const int q0  = qt * BM;
    const int nkt = seq >> 6;                       // 64-wide kv tiles total
    const int nkt_this = (qt + 1) * (BM / BN);      // kv tiles needed

    // fill coords
    const int f_kv = tid >> 1;
    const int f_dp = (tid & 1) * 32;

    // ---- Q fill (once): fp32 gmem -> fp16 smem, scale*log2e folded ----
    {
        const float4* gq = reinterpret_cast<const float4*>(
            q + ((size_t)(q0 + tid) * NH + hh) * HD);
        const float sc = QK_SCALE * LOG2E;
        #pragma unroll
        for (int j = 0; j < 32; ++j) {
            float4 val = gq[j];
            const uint32_t off = (uint32_t)(tid * QKSTR + j * 2) * 4u;
            STSV2(q_b + off, pack_f16x2(val.x * sc, val.y * sc),
                             pack_f16x2(val.z * sc, val.w * sc));
        }
    }

    // ---- async prefetch of K/V tile kt into buffer bsel ----
    auto prefetch_kv = [&](int kt, int bsel) {
        const uint32_t* srcK =
            Kh_g + ((size_t)(kt * BN + f_kv) * NKVH + kvh) * 64 + f_dp;
        const uint32_t dstK = k_b[bsel] + (uint32_t)(f_kv * QKSTR + f_dp) * 4u;
        #pragma unroll
        for (int j = 0; j < 8; ++j)
            CPASYNC16(dstK + j * 16u, srcK + j * 4);
        const uint32_t* srcV =
            VT_g + ((size_t)(kvh * nkt + kt) * HD + tid) * 32;
        const uint32_t dstV = v_b[bsel] + (uint32_t)(tid * VSTR) * 4u;
        #pragma unroll
        for (int j = 0; j < 8; ++j)
            CPASYNC16(dstV + j * 16u, srcV + j * 4);
    };

    prefetch_kv(0, 0);
    CPASYNC_COMMIT();

    // Per-thread rows: mt in {0,1}, hb in {0,1} -> row wid*32 + mt*16 + g + hb*8
    float m_s[2][2] = { { -INFINITY, -INFINITY }, { -INFINITY, -INFINITY } };
    float l_s[2][2] = { { 0.f, 0.f }, { 0.f, 0.f } };
    float o[2][16][4];
    #pragma unroll
    for (int mt = 0; mt < 2; ++mt)
        #pragma unroll
        for (int nt = 0; nt < 16; ++nt)
            #pragma unroll
            for (int j = 0; j < 4; ++j) o[mt][nt][j] = 0.f;

    for (int kt = 0; kt < nkt_this; ++kt) {
        CPASYNC_WAIT0();     // tile kt copy complete (this thread)
        __syncthreads();     // all threads' copies visible; prev compute done

        // overlap: start copying tile kt+1 into the other buffer
        if (kt + 1 < nkt_this) {
            prefetch_kv(kt + 1, (kt + 1) & 1);
            CPASYNC_COMMIT();
        }
        const uint32_t kb = k_b[kt & 1];
        const uint32_t vb = v_b[kt & 1];

        // ---- gemm1: S = Q * K^T (fp16, warp: 32x64) ----
        float c1[2][8][4];
        #pragma unroll
        for (int mt = 0; mt < 2; ++mt)
            #pragma unroll
            for (int nt = 0; nt < 8; ++nt)
                #pragma unroll
                for (int j = 0; j < 4; ++j) c1[mt][nt][j] = 0.f;

        #pragma unroll
        for (int kc = 0; kc < 8; ++kc) {
            uint32_t aH[2][4], bH[8][2];
            #pragma unroll
            for (int mt = 0; mt < 2; ++mt) {
                const uint32_t offA = (uint32_t)((wid * 32 + mt * 16 + (lane & 15)) * QKSTR
                                                 + kc * 8 + (lane >> 4) * 4) * 4u;
                LDMX4(aH[mt], q_b + offA);
            }
            #pragma unroll
            for (int t = 0; t < 4; ++t) {
                const uint32_t offB = (uint32_t)((t * 16 + ((lane >> 4) & 1) * 8 + (lane & 7)) * QKSTR
                                                 + kc * 8 + ((lane >> 3) & 1) * 4) * 4u;
                uint32_t rh[4];
                LDMX4(rh, kb + offB);
                bH[2*t][0] = rh[0]; bH[2*t][1] = rh[1]; bH[2*t+1][0] = rh[2]; bH[2*t+1][1] = rh[3];
            }
            #pragma unroll
            for (int mt = 0; mt < 2; ++mt)
                #pragma unroll
                for (int nt = 0; nt < 8; ++nt)
                    MMA_F16(c1[mt][nt], aH[mt], bH[nt]);
        }

        // ---- mask (partial tiles) + online softmax (rows warp-local) ----
        const bool need_mask = (kt * BN + BN - 1) > (q0 + wid * 32);
        #pragma unroll
        for (int mt = 0; mt < 2; ++mt) {
            #pragma unroll
            for (int hb = 0; hb < 2; ++hb) {
                const int qi = q0 + wid * 32 + mt * 16 + g + hb * 8;
                if (need_mask) {
                    #pragma unroll
                    for (int nt = 0; nt < 8; ++nt) {
                        const int kj = kt * BN + nt * 8 + 2 * tg;
                        if (kj + 0 > qi) c1[mt][nt][hb * 2 + 0] = -INFINITY;
                        if (kj + 1 > qi) c1[mt][nt][hb * 2 + 1] = -INFINITY;
                    }
                }
                float mx = -INFINITY;
                #pragma unroll
                for (int nt = 0; nt < 8; ++nt)
                    mx = fmaxf(mx, fmaxf(c1[mt][nt][hb * 2], c1[mt][nt][hb * 2 + 1]));
                mx = fmaxf(mx, __shfl_xor_sync(0xffffffffu, mx, 1));
                mx = fmaxf(mx, __shfl_xor_sync(0xffffffffu, mx, 2));

                const float m_new = fmaxf(m_s[mt][hb], mx);   // finite: col<=row exists
                const float alpha = ex2(m_s[mt][hb] - m_new);
                m_s[mt][hb] = m_new;

                float rs = 0.f;
                #pragma unroll
                for (int nt = 0; nt < 8; ++nt) {
                    float p0 = ex2(c1[mt][nt][hb * 2 + 0] - m_new);
                    float p1 = ex2(c1[mt][nt][hb * 2 + 1] - m_new);
                    c1[mt][nt][hb * 2 + 0] = p0;
                    c1[mt][nt][hb * 2 + 1] = p1;
                    rs += p0 + p1;
                }
                rs += __shfl_xor_sync(0xffffffffu, rs, 1);
                rs += __shfl_xor_sync(0xffffffffu, rs, 2);
                l_s[mt][hb] = l_s[mt][hb] * alpha + rs;

                #pragma unroll
                for (int nt = 0; nt < 16; ++nt) {
                    o[mt][nt][hb * 2 + 0] *= alpha;
                    o[mt][nt][hb * 2 + 1] *= alpha;
                }
            }
        }

        // ---- gemm2: O += P V. P packed from c1 registers; V frags shared by mt ----
        #pragma unroll
        for (int kc = 0; kc < 4; ++kc) {
            uint32_t aP[2][4];
            #pragma unroll
            for (int mt = 0; mt < 2; ++mt) {
                aP[mt][0] = pack_f16x2(c1[mt][2*kc+0][0], c1[mt][2*kc+0][1]);
                aP[mt][1] = pack_f16x2(c1[mt][2*kc+0][2], c1[mt][2*kc+0][3]);
                aP[mt][2] = pack_f16x2(c1[mt][2*kc+1][0], c1[mt][2*kc+1][1]);
                aP[mt][3] = pack_f16x2(c1[mt][2*kc+1][2], c1[mt][2*kc+1][3]);
            }
            #pragma unroll
            for (int t = 0; t < 8; ++t) {
                const uint32_t offV = (uint32_t)((t * 16 + ((lane >> 4) & 1) * 8 + (lane & 7)) * VSTR
                                                 + kc * 8 + ((lane >> 3) & 1) * 4) * 4u;
                uint32_t rv[4];
                LDMX4(rv, vb + offV);
                uint32_t b0[2] = { rv[0], rv[1] }, b1[2] = { rv[2], rv[3] };
                #pragma unroll
                for (int mt = 0; mt < 2; ++mt) {
                    MMA_F16(o[mt][2 * t + 0], aP[mt], b0);
                    MMA_F16(o[mt][2 * t + 1], aP[mt], b1);
                }
            }
        }
    }

    // ---- Epilogue: normalize, store ----
    #pragma unroll
    for (int mt = 0; mt < 2; ++mt)
        #pragma unroll
        for (int hb = 0; hb < 2; ++hb) {
            const float inv = 1.f / l_s[mt][hb];
            const int grow = q0 + wid * 32 + mt * 16 + g + hb * 8;
            float* obase = out + ((size_t)grow * NH + hh) * HD + 2 * tg;
            #pragma unroll
            for (int nt = 0; nt < 16; ++nt) {
                float2 val = make_float2(o[mt][nt][hb * 2 + 0] * inv,
                                         o[mt][nt][hb * 2 + 1] * inv);
                *reinterpret_cast<float2*>(obase + nt * 8) = val;
            }
        }
}

extern "C" void kernel_launch(void* const* d_in, const int* in_sizes, int n_in,
                              void* d_out, int out_size)
{
    const float* q = (const float*)d_in[0];
    const float* k = (const float*)d_in[1];
    const float* v = (const float*)d_in[2];
    float* out = (float*)d_out;

    const int seq = in_sizes[0] / (NH * HD);

    const int n_pairs = seq * NKVH * 64;
    convert_k_kernel<<<(n_pairs + 255) / 256, 256>>>(k, n_pairs);
    convert_v_kernel<<<dim3(seq / BN, NKVH), 128>>>(v);

    cudaFuncSetAttribute(attn_mma_kernel,
                         cudaFuncAttributeMaxDynamicSharedMemorySize, SMEM_BYTES);

    dim3 grid(seq / BM, NH);
    attn_mma_kernel<<<grid, 128, SMEM_BYTES>>>(q, out, seq);
}